// round 12
// baseline (speedup 1.0000x reference)
#include <cuda_runtime.h>
#include <cuda_fp16.h>
#include <stdint.h>
#include <math.h>

#define S 2048
#define D 2048
#define H 16
#define HD 128
#define II 8192
#define EPS 1e-5f

typedef __half hlf;

// ---------------- scratch (static device globals; no allocation) ----------
__device__ float g_x1  [(size_t)S * D];
__device__ hlf g_qkvh[(size_t)S * 3 * D];
__device__ hlf g_nxh [(size_t)S * D];
__device__ hlf g_ath [(size_t)S * D];
__device__ hlf g_nx2h[(size_t)S * D];
__device__ hlf g_gh  [(size_t)S * II];
__device__ hlf g_wqkvh[(size_t)D * 3 * D];
__device__ hlf g_woh [(size_t)D * D];
__device__ hlf g_w13h[(size_t)D * 2 * II];   // column-interleaved w1/w3
__device__ hlf g_w2h [(size_t)II * D];

// ---------------- PTX helpers ---------------------------------------------
__device__ __forceinline__ uint32_t smem_u32(const void* p)
{
    uint32_t a;
    asm("{ .reg .u64 t; cvta.to.shared.u64 t, %1; cvt.u32.u64 %0, t; }"
        : "=r"(a) : "l"(p));
    return a;
}

__device__ __forceinline__ void cpa16(uint32_t dst, const void* src)
{
    asm volatile("cp.async.cg.shared.global [%0], [%1], 16;"
                 :: "r"(dst), "l"(src));
}
#define CPA_COMMIT() asm volatile("cp.async.commit_group;" ::: "memory")
#define CPA_WAIT(n)  asm volatile("cp.async.wait_group %0;" :: "n"(n) : "memory")

__device__ __forceinline__ void ldm4u(unsigned int* r, uint32_t a)
{
    asm volatile("ldmatrix.sync.aligned.m8n8.x4.shared.b16 {%0,%1,%2,%3},[%4];"
                 : "=r"(r[0]), "=r"(r[1]), "=r"(r[2]), "=r"(r[3]) : "r"(a));
}
__device__ __forceinline__ void ldm4tu(unsigned int* r, uint32_t a)
{
    asm volatile("ldmatrix.sync.aligned.m8n8.x4.trans.shared.b16 {%0,%1,%2,%3},[%4];"
                 : "=r"(r[0]), "=r"(r[1]), "=r"(r[2]), "=r"(r[3]) : "r"(a));
}
__device__ __forceinline__ void mma16816(float* d, const unsigned int* a,
                                         const unsigned int* b)
{
    asm volatile(
        "mma.sync.aligned.m16n8k16.row.col.f32.f16.f16.f32 "
        "{%0,%1,%2,%3},{%4,%5,%6,%7},{%8,%9},{%0,%1,%2,%3};"
        : "+f"(d[0]), "+f"(d[1]), "+f"(d[2]), "+f"(d[3])
        : "r"(a[0]), "r"(a[1]), "r"(a[2]), "r"(a[3]), "r"(b[0]), "r"(b[1]));
}

__device__ __forceinline__ unsigned pack_h2(float a, float b)
{
    __half2 t = __floats2half2_rn(a, b);
    return *reinterpret_cast<unsigned*>(&t);
}

// ---------------- fp16 GEMM, cp.async 3-stage pipeline, k128 chunks --------
// C[128,128] = A[M,K] * B[K,N].
// Out modes: Cf fp32 (+Res) | Chf fp16 | silu: fp16 silu(c0)*c1 on interleaved
// column pairs (output width = tile/2, ldc = out row stride).
// Stage 64KB: A 128x128 @0 (32K, 256B rows), B 128x128 @32768 (two 16K halves).
#define STG 65536
#define GSMEM (3 * STG)

__device__ __forceinline__ void stage8(
    uint32_t sb,
    const hlf* __restrict__ Ah, int lda,
    const hlf* __restrict__ Bh, int ldb,
    int row0, int col0, int k0, int tid)
{
#pragma unroll
    for (int j = 0; j < 8; j++) {
        const int id = tid + j * 256;
        const int r = id >> 4, c = id & 15;
        const uint32_t off = (uint32_t)(r * 256 + ((c ^ (r & 7)) * 16));
        cpa16(sb + off, Ah + (size_t)(row0 + r) * lda + k0 + c * 8);
    }
#pragma unroll
    for (int j = 0; j < 8; j++) {
        const int id = tid + j * 256;
        const int r = id >> 4, c = id & 15;
        const int sub = c >> 3;
        const uint32_t off = (uint32_t)(32768 + sub * 16384 + r * 128
                                        + (((c & 7) ^ (r & 7)) * 16));
        cpa16(sb + off, Bh + (size_t)(k0 + r) * ldb + col0 + c * 8);
    }
}

__global__ void __launch_bounds__(256) tc8_gemm(
    const hlf* __restrict__ Ah, int lda,
    const hlf* __restrict__ Bh, int ldb,
    const float* __restrict__ Res, int ldres,
    float* __restrict__ Cf, hlf* __restrict__ Chf, int ldc, int K, int silu)
{
    extern __shared__ char smem[];
    const uint32_t sbase = smem_u32(smem);

    const int tid  = threadIdx.x;
    const int lane = tid & 31;
    const int wid  = tid >> 5;
    const int wm   = wid >> 1;
    const int wn   = wid & 1;
    const int row0 = blockIdx.y * 128;
    const int col0 = blockIdx.x * 128;

    const int nch = K >> 7;   // K multiple of 128, nch >= 2 for all our shapes

    float acc[2][8][4];
#pragma unroll
    for (int m = 0; m < 2; m++)
#pragma unroll
        for (int n = 0; n < 8; n++)
#pragma unroll
            for (int i = 0; i < 4; i++) acc[m][n][i] = 0.f;

    stage8(sbase, Ah, lda, Bh, ldb, row0, col0, 0, tid);
    CPA_COMMIT();
    stage8(sbase + STG, Ah, lda, Bh, ldb, row0, col0, 128, tid);
    CPA_COMMIT();

    for (int ch = 0; ch < nch; ch++) {
        if (ch + 1 < nch) { CPA_WAIT(1); } else { CPA_WAIT(0); }
        __syncthreads();

        if (ch + 2 < nch) {
            stage8(sbase + ((ch + 2) % 3) * STG, Ah, lda, Bh, ldb,
                   row0, col0, (ch + 2) * 128, tid);
            CPA_COMMIT();
        }

        const uint32_t base = sbase + (ch % 3) * STG;

#pragma unroll
        for (int kk = 0; kk < 128; kk += 16) {
            unsigned int ah[2][4];
#pragma unroll
            for (int mt = 0; mt < 2; mt++) {
                const int m  = wm * 32 + mt * 16 + (lane & 15);
                const int cc = ((kk >> 3) + (lane >> 4)) ^ (m & 7);
                ldm4u(ah[mt], base + (uint32_t)(m * 256 + cc * 16));
            }
#pragma unroll
            for (int g = 0; g < 4; g++) {
                const int kr = kk + (lane & 15);
                const int c  = wn * 8 + g * 2 + (lane >> 4);
                const int sub = c >> 3;
                const int cw  = (c & 7) ^ (kr & 7);
                const uint32_t a = base + 32768u
                    + (uint32_t)(sub * 16384 + kr * 128 + cw * 16);
                unsigned int r4[4];
                ldm4tu(r4, a);
                unsigned int b0[2] = { r4[0], r4[1] };
                unsigned int b1[2] = { r4[2], r4[3] };
#pragma unroll
                for (int mt = 0; mt < 2; mt++) {
                    mma16816(acc[mt][2 * g],     ah[mt], b0);
                    mma16816(acc[mt][2 * g + 1], ah[mt], b1);
                }
            }
        }
    }

#pragma unroll
    for (int mt = 0; mt < 2; mt++) {
        const int r0 = row0 + wm * 32 + mt * 16 + (lane >> 2);
#pragma unroll
        for (int nt = 0; nt < 8; nt++) {
            const int c = col0 + wn * 64 + nt * 8 + (lane & 3) * 2;
            float2 v0 = make_float2(acc[mt][nt][0], acc[mt][nt][1]);
            float2 v1 = make_float2(acc[mt][nt][2], acc[mt][nt][3]);
            if (silu) {
                // interleaved (h1, h3) pair -> silu(h1)*h3, out col = c/2
                const int co = c >> 1;
                Chf[(size_t)r0 * ldc + co] =
                    __float2half_rn(v0.x / (1.f + __expf(-v0.x)) * v0.y);
                Chf[(size_t)(r0 + 8) * ldc + co] =
                    __float2half_rn(v1.x / (1.f + __expf(-v1.x)) * v1.y);
            } else if (Cf) {
                if (Res) {
                    const float2 q0 = *reinterpret_cast<const float2*>(
                        Res + (size_t)r0 * ldres + c);
                    const float2 q1 = *reinterpret_cast<const float2*>(
                        Res + (size_t)(r0 + 8) * ldres + c);
                    v0.x += q0.x; v0.y += q0.y; v1.x += q1.x; v1.y += q1.y;
                }
                *reinterpret_cast<float2*>(Cf + (size_t)r0 * ldc + c) = v0;
                *reinterpret_cast<float2*>(Cf + (size_t)(r0 + 8) * ldc + c) = v1;
            } else {
                *reinterpret_cast<unsigned*>(Chf + (size_t)r0 * ldc + c) =
                    pack_h2(v0.x, v0.y);
                *reinterpret_cast<unsigned*>(Chf + (size_t)(r0 + 8) * ldc + c) =
                    pack_h2(v1.x, v1.y);
            }
        }
    }
}

// ---------------- flash attention (fp16, qkv packed [S,3D]) ----------------
#define FSMEM (32768 + 2 * 32768)
#define LDQ (3 * D)

__device__ __forceinline__ void fa_stage_kv(
    uint32_t dst, const hlf* __restrict__ kh, const hlf* __restrict__ vh,
    int krow0, int hd0, int tid)
{
#pragma unroll
    for (int j = 0; j < 4; j++) {
        const int id = tid + j * 256;
        const int r = id >> 4, c = id & 15;
        const uint32_t off = (uint32_t)(r * 256 + ((c ^ (r & 7)) * 16));
        const size_t g = (size_t)(krow0 + r) * LDQ + hd0 + c * 8;
        cpa16(dst + off, kh + g);
        cpa16(dst + 16384 + off, vh + g);
    }
}

__global__ void __launch_bounds__(256, 1) flash_attn(
    const hlf* __restrict__ qkv, hlf* __restrict__ ath)
{
    extern __shared__ char smem[];
    const uint32_t sb = smem_u32(smem);
    const int qb  = gridDim.x - 1 - blockIdx.x;   // heavy blocks first
    const int hd0 = blockIdx.y * HD;
    const int q0  = qb * 128;
    const int tid = threadIdx.x, lane = tid & 31, w = tid >> 5;
    const float iscale = 0.08838834764831845f;    // 1/sqrt(128)

    const hlf* qh = qkv;
    const hlf* kh = qkv + D;
    const hlf* vh = qkv + 2 * D;

#pragma unroll
    for (int j = 0; j < 8; j++) {
        const int id = tid + j * 256;
        const int r = id >> 4, c = id & 15;
        const uint32_t off = (uint32_t)(r * 256 + ((c ^ (r & 7)) * 16));
        cpa16(sb + off, qh + (size_t)(q0 + r) * LDQ + hd0 + c * 8);
    }
    fa_stage_kv(sb + 32768, kh, vh, 0, hd0, tid);
    CPA_COMMIT();

    const int nkt = 2 * (qb + 1);

    float m0 = -1e30f, m1 = -1e30f, l0 = 0.f, l1 = 0.f;
    float o[16][4];
#pragma unroll
    for (int nt = 0; nt < 16; nt++)
#pragma unroll
        for (int i = 0; i < 4; i++) o[nt][i] = 0.f;

    const int rloc = w * 16 + (lane & 15);
    const int rowg = q0 + w * 16 + (lane >> 2);

    for (int j = 0; j < nkt; j++) {
        __syncthreads();
        if (j + 1 < nkt) {
            fa_stage_kv(sb + 32768u + ((j + 1) & 1) * 32768u,
                        kh, vh, (j + 1) * 64, hd0, tid);
            CPA_COMMIT();
            CPA_WAIT(1);
        } else {
            CPA_WAIT(0);
        }
        __syncthreads();

        const uint32_t kb = sb + 32768u + (j & 1) * 32768u;

        // ---- S = Q K^T ----
        float s[8][4];
#pragma unroll
        for (int nt = 0; nt < 8; nt++)
#pragma unroll
            for (int i = 0; i < 4; i++) s[nt][i] = 0.f;

#pragma unroll
        for (int ks = 0; ks < 8; ks++) {
            unsigned int aq[4];
            const int cq = (2 * ks + (lane >> 4)) ^ (rloc & 7);
            ldm4u(aq, sb + (uint32_t)(rloc * 256 + cq * 16));
#pragma unroll
            for (int ng = 0; ng < 4; ng++) {
                const int rn = ng * 16 + (lane & 15);
                const int cn = (2 * ks + (lane >> 4)) ^ (rn & 7);
                unsigned int r[4];
                ldm4u(r, kb + (uint32_t)(rn * 256 + cn * 16));
                unsigned int b0[2] = { r[0], r[2] };
                unsigned int b1[2] = { r[1], r[3] };
                mma16816(s[2 * ng],     aq, b0);
                mma16816(s[2 * ng + 1], aq, b1);
            }
        }

        // ---- scale + causal mask + online softmax ----
        float mx0 = -1e30f, mx1 = -1e30f;
#pragma unroll
        for (int nt = 0; nt < 8; nt++) {
            const int col = j * 64 + nt * 8 + (lane & 3) * 2;
            s[nt][0] = (col     <= rowg)     ? s[nt][0] * iscale : -1e30f;
            s[nt][1] = (col + 1 <= rowg)     ? s[nt][1] * iscale : -1e30f;
            s[nt][2] = (col     <= rowg + 8) ? s[nt][2] * iscale : -1e30f;
            s[nt][3] = (col + 1 <= rowg + 8) ? s[nt][3] * iscale : -1e30f;
            mx0 = fmaxf(mx0, fmaxf(s[nt][0], s[nt][1]));
            mx1 = fmaxf(mx1, fmaxf(s[nt][2], s[nt][3]));
        }
        mx0 = fmaxf(mx0, __shfl_xor_sync(0xffffffffu, mx0, 1));
        mx0 = fmaxf(mx0, __shfl_xor_sync(0xffffffffu, mx0, 2));
        mx1 = fmaxf(mx1, __shfl_xor_sync(0xffffffffu, mx1, 1));
        mx1 = fmaxf(mx1, __shfl_xor_sync(0xffffffffu, mx1, 2));
        const float nm0 = fmaxf(m0, mx0);
        const float nm1 = fmaxf(m1, mx1);
        const float al0 = __expf(m0 - nm0);
        const float al1 = __expf(m1 - nm1);
        m0 = nm0; m1 = nm1;

        float sum0 = 0.f, sum1 = 0.f;
#pragma unroll
        for (int nt = 0; nt < 8; nt++) {
            s[nt][0] = __expf(s[nt][0] - nm0);
            s[nt][1] = __expf(s[nt][1] - nm0);
            s[nt][2] = __expf(s[nt][2] - nm1);
            s[nt][3] = __expf(s[nt][3] - nm1);
            sum0 += s[nt][0] + s[nt][1];
            sum1 += s[nt][2] + s[nt][3];
        }
        sum0 += __shfl_xor_sync(0xffffffffu, sum0, 1);
        sum0 += __shfl_xor_sync(0xffffffffu, sum0, 2);
        sum1 += __shfl_xor_sync(0xffffffffu, sum1, 1);
        sum1 += __shfl_xor_sync(0xffffffffu, sum1, 2);
        l0 = l0 * al0 + sum0;
        l1 = l1 * al1 + sum1;

#pragma unroll
        for (int nt = 0; nt < 16; nt++) {
            o[nt][0] *= al0; o[nt][1] *= al0;
            o[nt][2] *= al1; o[nt][3] *= al1;
        }

        // ---- PV ----
#pragma unroll
        for (int ks = 0; ks < 4; ks++) {
            unsigned int ph[4];
            ph[0] = pack_h2(s[2 * ks][0],     s[2 * ks][1]);
            ph[1] = pack_h2(s[2 * ks][2],     s[2 * ks][3]);
            ph[2] = pack_h2(s[2 * ks + 1][0], s[2 * ks + 1][1]);
            ph[3] = pack_h2(s[2 * ks + 1][2], s[2 * ks + 1][3]);
#pragma unroll
            for (int ng = 0; ng < 8; ng++) {
                const int kr = ks * 16 + (lane & 15);
                const int cv = (ng * 2 + (lane >> 4)) ^ (kr & 7);
                unsigned int r[4];
                ldm4tu(r, kb + 16384u + (uint32_t)(kr * 256 + cv * 16));
                unsigned int b0[2] = { r[0], r[1] };
                unsigned int b1[2] = { r[2], r[3] };
                mma16816(o[2 * ng],     ph, b0);
                mma16816(o[2 * ng + 1], ph, b1);
            }
        }
    }

    const float inv0 = 1.f / l0;
    const float inv1 = 1.f / l1;
#pragma unroll
    for (int nt = 0; nt < 16; nt++) {
        const int c = hd0 + nt * 8 + (lane & 3) * 2;
        *reinterpret_cast<unsigned*>(ath + (size_t)rowg * D + c) =
            pack_h2(o[nt][0] * inv0, o[nt][1] * inv0);
        *reinterpret_cast<unsigned*>(ath + (size_t)(rowg + 8) * D + c) =
            pack_h2(o[nt][2] * inv1, o[nt][3] * inv1);
    }
}

// ---------------- elementwise kernels --------------------------------------
// 4 float4s per thread, stride-256 (coalesced, MLP=4)
__global__ __launch_bounds__(256) void split_pack_h(
    const float* __restrict__ in, hlf* __restrict__ hi,
    int nsrc, int ndst, int coff)
{
    const size_t base = (size_t)blockIdx.x * 1024 + threadIdx.x;
    float4 v[4];
#pragma unroll
    for (int i = 0; i < 4; i++)
        v[i] = reinterpret_cast<const float4*>(in)[base + i * 256];
#pragma unroll
    for (int i = 0; i < 4; i++) {
        const size_t e   = (base + i * 256) * 4;
        const size_t row = e / nsrc;
        const size_t col = e % nsrc;
        const size_t o2  = (row * ndst + coff + col) / 2;
        reinterpret_cast<unsigned*>(hi)[o2]     = pack_h2(v[i].x, v[i].y);
        reinterpret_cast<unsigned*>(hi)[o2 + 1] = pack_h2(v[i].z, v[i].w);
    }
}

// interleave w1/w3 columns: out[k][2j]=w1[k][j], out[k][2j+1]=w3[k][j]
__global__ __launch_bounds__(256) void pack_w13i(
    const float* __restrict__ w1, const float* __restrict__ w3,
    hlf* __restrict__ out)
{
    const size_t base = (size_t)blockIdx.x * 1024 + threadIdx.x;
#pragma unroll
    for (int i = 0; i < 4; i++) {
        const size_t i4 = base + i * 256;
        const float4 v1 = reinterpret_cast<const float4*>(w1)[i4];
        const float4 v3 = reinterpret_cast<const float4*>(w3)[i4];
        const size_t e   = i4 * 4;
        const size_t row = e / II;
        const size_t col = e % II;
        uint4 o;
        o.x = pack_h2(v1.x, v3.x);
        o.y = pack_h2(v1.y, v3.y);
        o.z = pack_h2(v1.z, v3.z);
        o.w = pack_h2(v1.w, v3.w);
        *reinterpret_cast<uint4*>(out + row * (2 * II) + 2 * col) = o;
    }
}

__global__ __launch_bounds__(256) void rmsnorm_h(
    const float* __restrict__ x, const float* __restrict__ w,
    hlf* __restrict__ hi)
{
    const int row = blockIdx.x;
    const float4* xr = reinterpret_cast<const float4*>(x + (size_t)row * D);
    float4 va[2];
    float ss = 0.f;
#pragma unroll
    for (int i = 0; i < 2; i++) {
        va[i] = xr[threadIdx.x + i * 256];
        ss += va[i].x * va[i].x + va[i].y * va[i].y +
              va[i].z * va[i].z + va[i].w * va[i].w;
    }
    __shared__ float red[256];
    red[threadIdx.x] = ss;
    __syncthreads();
    for (int s = 128; s > 0; s >>= 1) {
        if (threadIdx.x < s) red[threadIdx.x] += red[threadIdx.x + s];
        __syncthreads();
    }
    const float r = rsqrtf(red[0] * (1.0f / D) + EPS);
    const float4* w4 = reinterpret_cast<const float4*>(w);
#pragma unroll
    for (int i = 0; i < 2; i++) {
        const float4 wv = w4[threadIdx.x + i * 256];
        const size_t o2 = ((size_t)row * D) / 2 + (threadIdx.x + i * 256) * 2;
        reinterpret_cast<unsigned*>(hi)[o2] =
            pack_h2(va[i].x * r * wv.x, va[i].y * r * wv.y);
        reinterpret_cast<unsigned*>(hi)[o2 + 1] =
            pack_h2(va[i].z * r * wv.z, va[i].w * r * wv.w);
    }
}

// in-place RoPE on q,k sections of packed fp16 qkv [S, 3D]
__global__ __launch_bounds__(256) void rope_inplace_h(
    hlf* __restrict__ qkv,
    const float* __restrict__ cs, const float* __restrict__ sn)
{
    const int idx = blockIdx.x * 256 + threadIdx.x;   // over S*D/2
    const int s   = idx / (D / 2);
    const int rem = idx % (D / 2);
    const int h   = rem >> 6;
    const int d   = rem & 63;
    const size_t p0 = (size_t)s * (3 * D) + h * HD + d;
    const size_t p1 = p0 + 64;
    const float c0 = cs[s * HD + d],      s0 = sn[s * HD + d];
    const float c1 = cs[s * HD + d + 64], s1 = sn[s * HD + d + 64];

    const float q0 = __half2float(qkv[p0]), q1 = __half2float(qkv[p1]);
    qkv[p0] = __float2half_rn(q0 * c0 - q1 * s0);
    qkv[p1] = __float2half_rn(q1 * c1 + q0 * s1);
    const float k0 = __half2float(qkv[p0 + D]), k1 = __half2float(qkv[p1 + D]);
    qkv[p0 + D] = __float2half_rn(k0 * c0 - k1 * s0);
    qkv[p1 + D] = __float2half_rn(k1 * c1 + k0 * s1);
}

// ---------------- launch ---------------------------------------------------
extern "C" void kernel_launch(void* const* d_in, const int* in_sizes, int n_in,
                              void* d_out, int out_size)
{
    const float* x    = (const float*)d_in[0];
    const float* fcos = (const float*)d_in[2];
    const float* fsin = (const float*)d_in[3];
    const float* wq   = (const float*)d_in[4];
    const float* wk   = (const float*)d_in[5];
    const float* wv   = (const float*)d_in[6];
    const float* wo   = (const float*)d_in[7];
    const float* w1   = (const float*)d_in[8];
    const float* w2   = (const float*)d_in[9];
    const float* w3   = (const float*)d_in[10];
    const float* anw  = (const float*)d_in[11];
    const float* fnw  = (const float*)d_in[12];
    float* out = (float*)d_out;

    float *x1;
    hlf *qkvh, *nxh, *ath, *nx2h, *gh;
    hlf *wqkvh, *woh, *w13h, *w2h;

    cudaGetSymbolAddress((void**)&x1,   g_x1);
    cudaGetSymbolAddress((void**)&qkvh, g_qkvh);
    cudaGetSymbolAddress((void**)&nxh,  g_nxh);
    cudaGetSymbolAddress((void**)&ath,  g_ath);
    cudaGetSymbolAddress((void**)&nx2h, g_nx2h);
    cudaGetSymbolAddress((void**)&gh,   g_gh);
    cudaGetSymbolAddress((void**)&wqkvh, g_wqkvh);
    cudaGetSymbolAddress((void**)&woh,  g_woh);
    cudaGetSymbolAddress((void**)&w13h, g_w13h);
    cudaGetSymbolAddress((void**)&w2h,  g_w2h);

    cudaFuncSetAttribute(tc8_gemm,
        cudaFuncAttributeMaxDynamicSharedMemorySize, GSMEM);
    cudaFuncSetAttribute(flash_attn,
        cudaFuncAttributeMaxDynamicSharedMemorySize, FSMEM);

    const dim3 gQkv(3 * D / 128, S / 128);       // 48x16
    const dim3 gProj(D / 128, S / 128);          // 16x16
    const dim3 gW13(2 * II / 128, S / 128);      // 128x16 (interleaved cols)
    const dim3 gFa (S / 128, H);                 // 16x16

    const int nDD = (D * D) / 4096;              // 4 float4/thread
    const int nDI = (D * II) / 4096;

    split_pack_h<<<nDD, 256>>>(wq, wqkvh, D, 3 * D, 0);
    split_pack_h<<<nDD, 256>>>(wk, wqkvh, D, 3 * D, D);
    split_pack_h<<<nDD, 256>>>(wv, wqkvh, D, 3 * D, 2 * D);
    split_pack_h<<<nDD, 256>>>(wo, woh, D, D, 0);
    pack_w13i<<<nDI, 256>>>(w1, w3, w13h);
    split_pack_h<<<nDI, 256>>>(w2, w2h, D, D, 0);

    rmsnorm_h<<<S, 256>>>(x, anw, nxh);

    // qkv projection -> fp16 [S, 3D]
    tc8_gemm<<<gQkv, 256, GSMEM>>>(nxh, D, wqkvh, 3 * D,
                                   nullptr, 0, nullptr, qkvh, 3 * D, D, 0);

    rope_inplace_h<<<(S * D / 2) / 256, 256>>>(qkvh, fcos, fsin);

    flash_attn<<<gFa, 256, FSMEM>>>(qkvh, ath);

    tc8_gemm<<<gProj, 256, GSMEM>>>(ath, D, woh, D,
                                    x, D, x1, nullptr, D, D, 0);

    rmsnorm_h<<<S, 256>>>(x1, fnw, nx2h);

    // fused w13 + silu -> fp16 gh [S, II]
    tc8_gemm<<<gW13, 256, GSMEM>>>(nx2h, D, w13h, 2 * II,
                                   nullptr, 0, nullptr, gh, II, D, 1);

    tc8_gemm<<<gProj, 256, GSMEM>>>(gh, II, w2h, D,
                                    x1, D, out, nullptr, D, II, 0);
}

// round 14
// speedup vs baseline: 1.1388x; 1.1388x over previous
#include <cuda_runtime.h>
#include <cuda_fp16.h>
#include <stdint.h>
#include <math.h>

#define S 2048
#define D 2048
#define H 16
#define HD 128
#define II 8192
#define EPS 1e-5f

typedef __half hlf;

// ---------------- scratch (static device globals; no allocation) ----------
__device__ float g_x1  [(size_t)S * D];
__device__ hlf g_qkvh[(size_t)S * 3 * D];
__device__ hlf g_nxh [(size_t)S * D];
__device__ hlf g_ath [(size_t)S * D];
__device__ hlf g_nx2h[(size_t)S * D];
__device__ hlf g_gh  [(size_t)S * II];
__device__ hlf g_wqkvh[(size_t)D * 3 * D];
__device__ hlf g_woh [(size_t)D * D];
__device__ hlf g_w13h[(size_t)D * 2 * II];   // column-interleaved w1/w3
__device__ hlf g_w2h [(size_t)II * D];

// ---------------- PTX helpers ---------------------------------------------
__device__ __forceinline__ uint32_t smem_u32(const void* p)
{
    uint32_t a;
    asm("{ .reg .u64 t; cvta.to.shared.u64 t, %1; cvt.u32.u64 %0, t; }"
        : "=r"(a) : "l"(p));
    return a;
}

__device__ __forceinline__ void cpa16(uint32_t dst, const void* src)
{
    asm volatile("cp.async.cg.shared.global [%0], [%1], 16;"
                 :: "r"(dst), "l"(src));
}
#define CPA_COMMIT() asm volatile("cp.async.commit_group;" ::: "memory")
#define CPA_WAIT(n)  asm volatile("cp.async.wait_group %0;" :: "n"(n) : "memory")

__device__ __forceinline__ void ldm4u(unsigned int* r, uint32_t a)
{
    asm volatile("ldmatrix.sync.aligned.m8n8.x4.shared.b16 {%0,%1,%2,%3},[%4];"
                 : "=r"(r[0]), "=r"(r[1]), "=r"(r[2]), "=r"(r[3]) : "r"(a));
}
__device__ __forceinline__ void ldm4tu(unsigned int* r, uint32_t a)
{
    asm volatile("ldmatrix.sync.aligned.m8n8.x4.trans.shared.b16 {%0,%1,%2,%3},[%4];"
                 : "=r"(r[0]), "=r"(r[1]), "=r"(r[2]), "=r"(r[3]) : "r"(a));
}
__device__ __forceinline__ void mma16816(float* d, const unsigned int* a,
                                         const unsigned int* b)
{
    asm volatile(
        "mma.sync.aligned.m16n8k16.row.col.f32.f16.f16.f32 "
        "{%0,%1,%2,%3},{%4,%5,%6,%7},{%8,%9},{%0,%1,%2,%3};"
        : "+f"(d[0]), "+f"(d[1]), "+f"(d[2]), "+f"(d[3])
        : "r"(a[0]), "r"(a[1]), "r"(a[2]), "r"(a[3]), "r"(b[0]), "r"(b[1]));
}

__device__ __forceinline__ unsigned pack_h2(float a, float b)
{
    __half2 t = __floats2half2_rn(a, b);
    return *reinterpret_cast<unsigned*>(&t);
}

// ---------------- fp16 GEMM, cp.async 3-stage pipeline, k64 chunks ---------
// C[128,128] = A[M,K] * B[K,N].
// Out modes: Cf fp32 (+Res) | Chf fp16 | silu: fp16 silu(c0)*c1 on interleaved
// column pairs (output width = tile/2, ldc = out row stride).
// Stage 32KB: A 128x64 @0, B 64x128 @16384 (two 8K n-halves).
#define STG 32768
#define GSMEM (3 * STG)

__device__ __forceinline__ void stage8(
    uint32_t sb,
    const hlf* __restrict__ Ah, int lda,
    const hlf* __restrict__ Bh, int ldb,
    int row0, int col0, int k0, int tid)
{
#pragma unroll
    for (int j = 0; j < 4; j++) {
        const int id = tid + j * 256;
        const int r = id >> 3, c = id & 7;
        const uint32_t off = (uint32_t)(r * 128 + ((c ^ (r & 7)) * 16));
        cpa16(sb + off, Ah + (size_t)(row0 + r) * lda + k0 + c * 8);
    }
#pragma unroll
    for (int j = 0; j < 4; j++) {
        const int id = tid + j * 256;
        const int r = id >> 4, c = id & 15;
        const int sub = c >> 3;
        const uint32_t off = (uint32_t)(16384 + sub * 8192 + r * 128
                                        + (((c & 7) ^ (r & 7)) * 16));
        cpa16(sb + off, Bh + (size_t)(k0 + r) * ldb + col0 + c * 8);
    }
}

__global__ void __launch_bounds__(256) tc8_gemm(
    const hlf* __restrict__ Ah, int lda,
    const hlf* __restrict__ Bh, int ldb,
    const float* __restrict__ Res, int ldres,
    float* __restrict__ Cf, hlf* __restrict__ Chf, int ldc, int K, int silu)
{
    extern __shared__ char smem[];
    const uint32_t sbase = smem_u32(smem);

    const int tid  = threadIdx.x;
    const int lane = tid & 31;
    const int wid  = tid >> 5;
    const int wm   = wid >> 1;
    const int wn   = wid & 1;
    const int row0 = blockIdx.y * 128;
    const int col0 = blockIdx.x * 128;

    const int nch = K >> 6;

    float acc[2][8][4];
#pragma unroll
    for (int m = 0; m < 2; m++)
#pragma unroll
        for (int n = 0; n < 8; n++)
#pragma unroll
            for (int i = 0; i < 4; i++) acc[m][n][i] = 0.f;

    stage8(sbase, Ah, lda, Bh, ldb, row0, col0, 0, tid);
    CPA_COMMIT();
    stage8(sbase + STG, Ah, lda, Bh, ldb, row0, col0, 64, tid);
    CPA_COMMIT();

    for (int ch = 0; ch < nch; ch++) {
        if (ch + 1 < nch) { CPA_WAIT(1); } else { CPA_WAIT(0); }
        __syncthreads();

        if (ch + 2 < nch) {
            stage8(sbase + ((ch + 2) % 3) * STG, Ah, lda, Bh, ldb,
                   row0, col0, (ch + 2) * 64, tid);
            CPA_COMMIT();
        }

        const uint32_t base = sbase + (ch % 3) * STG;

#pragma unroll
        for (int kk = 0; kk < 64; kk += 16) {
            unsigned int ah[2][4];
#pragma unroll
            for (int mt = 0; mt < 2; mt++) {
                const int m  = wm * 32 + mt * 16 + (lane & 15);
                const int cc = ((kk >> 3) + (lane >> 4)) ^ (m & 7);
                ldm4u(ah[mt], base + (uint32_t)(m * 128 + cc * 16));
            }
#pragma unroll
            for (int g = 0; g < 4; g++) {
                const int kr = kk + (lane & 15);
                const int c  = wn * 8 + g * 2 + (lane >> 4);
                const int sub = c >> 3;
                const int cw  = (c & 7) ^ (kr & 7);
                const uint32_t a = base + 16384u
                    + (uint32_t)(sub * 8192 + kr * 128 + cw * 16);
                unsigned int r4[4];
                ldm4tu(r4, a);
                unsigned int b0[2] = { r4[0], r4[1] };
                unsigned int b1[2] = { r4[2], r4[3] };
#pragma unroll
                for (int mt = 0; mt < 2; mt++) {
                    mma16816(acc[mt][2 * g],     ah[mt], b0);
                    mma16816(acc[mt][2 * g + 1], ah[mt], b1);
                }
            }
        }
    }

#pragma unroll
    for (int mt = 0; mt < 2; mt++) {
        const int r0 = row0 + wm * 32 + mt * 16 + (lane >> 2);
#pragma unroll
        for (int nt = 0; nt < 8; nt++) {
            const int c = col0 + wn * 64 + nt * 8 + (lane & 3) * 2;
            float2 v0 = make_float2(acc[mt][nt][0], acc[mt][nt][1]);
            float2 v1 = make_float2(acc[mt][nt][2], acc[mt][nt][3]);
            if (silu) {
                // interleaved (h1, h3) pair -> silu(h1)*h3, out col = c/2
                const int co = c >> 1;
                Chf[(size_t)r0 * ldc + co] =
                    __float2half_rn(v0.x / (1.f + __expf(-v0.x)) * v0.y);
                Chf[(size_t)(r0 + 8) * ldc + co] =
                    __float2half_rn(v1.x / (1.f + __expf(-v1.x)) * v1.y);
            } else if (Cf) {
                if (Res) {
                    const float2 q0 = *reinterpret_cast<const float2*>(
                        Res + (size_t)r0 * ldres + c);
                    const float2 q1 = *reinterpret_cast<const float2*>(
                        Res + (size_t)(r0 + 8) * ldres + c);
                    v0.x += q0.x; v0.y += q0.y; v1.x += q1.x; v1.y += q1.y;
                }
                *reinterpret_cast<float2*>(Cf + (size_t)r0 * ldc + c) = v0;
                *reinterpret_cast<float2*>(Cf + (size_t)(r0 + 8) * ldc + c) = v1;
            } else {
                *reinterpret_cast<unsigned*>(Chf + (size_t)r0 * ldc + c) =
                    pack_h2(v0.x, v0.y);
                *reinterpret_cast<unsigned*>(Chf + (size_t)(r0 + 8) * ldc + c) =
                    pack_h2(v1.x, v1.y);
            }
        }
    }
}

// ---------------- flash attention (fp16, qkv packed [S,3D]) ----------------
#define FSMEM (32768 + 2 * 32768)
#define LDQ (3 * D)

__device__ __forceinline__ void fa_stage_kv(
    uint32_t dst, const hlf* __restrict__ kh, const hlf* __restrict__ vh,
    int krow0, int hd0, int tid)
{
#pragma unroll
    for (int j = 0; j < 4; j++) {
        const int id = tid + j * 256;
        const int r = id >> 4, c = id & 15;
        const uint32_t off = (uint32_t)(r * 256 + ((c ^ (r & 7)) * 16));
        const size_t g = (size_t)(krow0 + r) * LDQ + hd0 + c * 8;
        cpa16(dst + off, kh + g);
        cpa16(dst + 16384 + off, vh + g);
    }
}

__global__ void __launch_bounds__(256, 1) flash_attn(
    const hlf* __restrict__ qkv, hlf* __restrict__ ath)
{
    extern __shared__ char smem[];
    const uint32_t sb = smem_u32(smem);
    const int qb  = gridDim.x - 1 - blockIdx.x;   // heavy blocks first
    const int hd0 = blockIdx.y * HD;
    const int q0  = qb * 128;
    const int tid = threadIdx.x, lane = tid & 31, w = tid >> 5;
    const float iscale = 0.08838834764831845f;    // 1/sqrt(128)

    const hlf* qh = qkv;
    const hlf* kh = qkv + D;
    const hlf* vh = qkv + 2 * D;

#pragma unroll
    for (int j = 0; j < 8; j++) {
        const int id = tid + j * 256;
        const int r = id >> 4, c = id & 15;
        const uint32_t off = (uint32_t)(r * 256 + ((c ^ (r & 7)) * 16));
        cpa16(sb + off, qh + (size_t)(q0 + r) * LDQ + hd0 + c * 8);
    }
    fa_stage_kv(sb + 32768, kh, vh, 0, hd0, tid);
    CPA_COMMIT();

    const int nkt = 2 * (qb + 1);

    float m0 = -1e30f, m1 = -1e30f, l0 = 0.f, l1 = 0.f;
    float o[16][4];
#pragma unroll
    for (int nt = 0; nt < 16; nt++)
#pragma unroll
        for (int i = 0; i < 4; i++) o[nt][i] = 0.f;

    const int rloc = w * 16 + (lane & 15);
    const int rowg = q0 + w * 16 + (lane >> 2);

    for (int j = 0; j < nkt; j++) {
        __syncthreads();
        if (j + 1 < nkt) {
            fa_stage_kv(sb + 32768u + ((j + 1) & 1) * 32768u,
                        kh, vh, (j + 1) * 64, hd0, tid);
            CPA_COMMIT();
            CPA_WAIT(1);
        } else {
            CPA_WAIT(0);
        }
        __syncthreads();

        const uint32_t kb = sb + 32768u + (j & 1) * 32768u;

        // ---- S = Q K^T ----
        float s[8][4];
#pragma unroll
        for (int nt = 0; nt < 8; nt++)
#pragma unroll
            for (int i = 0; i < 4; i++) s[nt][i] = 0.f;

#pragma unroll
        for (int ks = 0; ks < 8; ks++) {
            unsigned int aq[4];
            const int cq = (2 * ks + (lane >> 4)) ^ (rloc & 7);
            ldm4u(aq, sb + (uint32_t)(rloc * 256 + cq * 16));
#pragma unroll
            for (int ng = 0; ng < 4; ng++) {
                const int rn = ng * 16 + (lane & 15);
                const int cn = (2 * ks + (lane >> 4)) ^ (rn & 7);
                unsigned int r[4];
                ldm4u(r, kb + (uint32_t)(rn * 256 + cn * 16));
                unsigned int b0[2] = { r[0], r[2] };
                unsigned int b1[2] = { r[1], r[3] };
                mma16816(s[2 * ng],     aq, b0);
                mma16816(s[2 * ng + 1], aq, b1);
            }
        }

        // ---- scale + causal mask + online softmax ----
        float mx0 = -1e30f, mx1 = -1e30f;
#pragma unroll
        for (int nt = 0; nt < 8; nt++) {
            const int col = j * 64 + nt * 8 + (lane & 3) * 2;
            s[nt][0] = (col     <= rowg)     ? s[nt][0] * iscale : -1e30f;
            s[nt][1] = (col + 1 <= rowg)     ? s[nt][1] * iscale : -1e30f;
            s[nt][2] = (col     <= rowg + 8) ? s[nt][2] * iscale : -1e30f;
            s[nt][3] = (col + 1 <= rowg + 8) ? s[nt][3] * iscale : -1e30f;
            mx0 = fmaxf(mx0, fmaxf(s[nt][0], s[nt][1]));
            mx1 = fmaxf(mx1, fmaxf(s[nt][2], s[nt][3]));
        }
        mx0 = fmaxf(mx0, __shfl_xor_sync(0xffffffffu, mx0, 1));
        mx0 = fmaxf(mx0, __shfl_xor_sync(0xffffffffu, mx0, 2));
        mx1 = fmaxf(mx1, __shfl_xor_sync(0xffffffffu, mx1, 1));
        mx1 = fmaxf(mx1, __shfl_xor_sync(0xffffffffu, mx1, 2));
        const float nm0 = fmaxf(m0, mx0);
        const float nm1 = fmaxf(m1, mx1);
        const float al0 = __expf(m0 - nm0);
        const float al1 = __expf(m1 - nm1);
        m0 = nm0; m1 = nm1;

        float sum0 = 0.f, sum1 = 0.f;
#pragma unroll
        for (int nt = 0; nt < 8; nt++) {
            s[nt][0] = __expf(s[nt][0] - nm0);
            s[nt][1] = __expf(s[nt][1] - nm0);
            s[nt][2] = __expf(s[nt][2] - nm1);
            s[nt][3] = __expf(s[nt][3] - nm1);
            sum0 += s[nt][0] + s[nt][1];
            sum1 += s[nt][2] + s[nt][3];
        }
        sum0 += __shfl_xor_sync(0xffffffffu, sum0, 1);
        sum0 += __shfl_xor_sync(0xffffffffu, sum0, 2);
        sum1 += __shfl_xor_sync(0xffffffffu, sum1, 1);
        sum1 += __shfl_xor_sync(0xffffffffu, sum1, 2);
        l0 = l0 * al0 + sum0;
        l1 = l1 * al1 + sum1;

#pragma unroll
        for (int nt = 0; nt < 16; nt++) {
            o[nt][0] *= al0; o[nt][1] *= al0;
            o[nt][2] *= al1; o[nt][3] *= al1;
        }

        // ---- PV ----
#pragma unroll
        for (int ks = 0; ks < 4; ks++) {
            unsigned int ph[4];
            ph[0] = pack_h2(s[2 * ks][0],     s[2 * ks][1]);
            ph[1] = pack_h2(s[2 * ks][2],     s[2 * ks][3]);
            ph[2] = pack_h2(s[2 * ks + 1][0], s[2 * ks + 1][1]);
            ph[3] = pack_h2(s[2 * ks + 1][2], s[2 * ks + 1][3]);
#pragma unroll
            for (int ng = 0; ng < 8; ng++) {
                const int kr = ks * 16 + (lane & 15);
                const int cv = (ng * 2 + (lane >> 4)) ^ (kr & 7);
                unsigned int r[4];
                ldm4tu(r, kb + 16384u + (uint32_t)(kr * 256 + cv * 16));
                unsigned int b0[2] = { r[0], r[1] };
                unsigned int b1[2] = { r[2], r[3] };
                mma16816(o[2 * ng],     ph, b0);
                mma16816(o[2 * ng + 1], ph, b1);
            }
        }
    }

    const float inv0 = 1.f / l0;
    const float inv1 = 1.f / l1;
#pragma unroll
    for (int nt = 0; nt < 16; nt++) {
        const int c = hd0 + nt * 8 + (lane & 3) * 2;
        *reinterpret_cast<unsigned*>(ath + (size_t)rowg * D + c) =
            pack_h2(o[nt][0] * inv0, o[nt][1] * inv0);
        *reinterpret_cast<unsigned*>(ath + (size_t)(rowg + 8) * D + c) =
            pack_h2(o[nt][2] * inv1, o[nt][3] * inv1);
    }
}

// ---------------- elementwise kernels --------------------------------------
// 4 float4s per thread, stride-256 (coalesced, MLP=4)
__global__ __launch_bounds__(256) void split_pack_h(
    const float* __restrict__ in, hlf* __restrict__ hi,
    int nsrc, int ndst, int coff)
{
    const size_t base = (size_t)blockIdx.x * 1024 + threadIdx.x;
    float4 v[4];
#pragma unroll
    for (int i = 0; i < 4; i++)
        v[i] = reinterpret_cast<const float4*>(in)[base + i * 256];
#pragma unroll
    for (int i = 0; i < 4; i++) {
        const size_t e   = (base + i * 256) * 4;
        const size_t row = e / nsrc;
        const size_t col = e % nsrc;
        const size_t o2  = (row * ndst + coff + col) / 2;
        reinterpret_cast<unsigned*>(hi)[o2]     = pack_h2(v[i].x, v[i].y);
        reinterpret_cast<unsigned*>(hi)[o2 + 1] = pack_h2(v[i].z, v[i].w);
    }
}

// interleave w1/w3 columns: out[k][2j]=w1[k][j], out[k][2j+1]=w3[k][j]
__global__ __launch_bounds__(256) void pack_w13i(
    const float* __restrict__ w1, const float* __restrict__ w3,
    hlf* __restrict__ out)
{
    const size_t base = (size_t)blockIdx.x * 1024 + threadIdx.x;
#pragma unroll
    for (int i = 0; i < 4; i++) {
        const size_t i4 = base + i * 256;
        const float4 v1 = reinterpret_cast<const float4*>(w1)[i4];
        const float4 v3 = reinterpret_cast<const float4*>(w3)[i4];
        const size_t e   = i4 * 4;
        const size_t row = e / II;
        const size_t col = e % II;
        uint4 o;
        o.x = pack_h2(v1.x, v3.x);
        o.y = pack_h2(v1.y, v3.y);
        o.z = pack_h2(v1.z, v3.z);
        o.w = pack_h2(v1.w, v3.w);
        *reinterpret_cast<uint4*>(out + row * (2 * II) + 2 * col) = o;
    }
}

__global__ __launch_bounds__(256) void rmsnorm_h(
    const float* __restrict__ x, const float* __restrict__ w,
    hlf* __restrict__ hi)
{
    const int row = blockIdx.x;
    const float4* xr = reinterpret_cast<const float4*>(x + (size_t)row * D);
    float4 va[2];
    float ss = 0.f;
#pragma unroll
    for (int i = 0; i < 2; i++) {
        va[i] = xr[threadIdx.x + i * 256];
        ss += va[i].x * va[i].x + va[i].y * va[i].y +
              va[i].z * va[i].z + va[i].w * va[i].w;
    }
    __shared__ float red[256];
    red[threadIdx.x] = ss;
    __syncthreads();
    for (int s = 128; s > 0; s >>= 1) {
        if (threadIdx.x < s) red[threadIdx.x] += red[threadIdx.x + s];
        __syncthreads();
    }
    const float r = rsqrtf(red[0] * (1.0f / D) + EPS);
    const float4* w4 = reinterpret_cast<const float4*>(w);
#pragma unroll
    for (int i = 0; i < 2; i++) {
        const float4 wv = w4[threadIdx.x + i * 256];
        const size_t o2 = ((size_t)row * D) / 2 + (threadIdx.x + i * 256) * 2;
        reinterpret_cast<unsigned*>(hi)[o2] =
            pack_h2(va[i].x * r * wv.x, va[i].y * r * wv.y);
        reinterpret_cast<unsigned*>(hi)[o2 + 1] =
            pack_h2(va[i].z * r * wv.z, va[i].w * r * wv.w);
    }
}

// in-place RoPE on q,k sections of packed fp16 qkv [S, 3D]
__global__ __launch_bounds__(256) void rope_inplace_h(
    hlf* __restrict__ qkv,
    const float* __restrict__ cs, const float* __restrict__ sn)
{
    const int idx = blockIdx.x * 256 + threadIdx.x;   // over S*D/2
    const int s   = idx / (D / 2);
    const int rem = idx % (D / 2);
    const int h   = rem >> 6;
    const int d   = rem & 63;
    const size_t p0 = (size_t)s * (3 * D) + h * HD + d;
    const size_t p1 = p0 + 64;
    const float c0 = cs[s * HD + d],      s0 = sn[s * HD + d];
    const float c1 = cs[s * HD + d + 64], s1 = sn[s * HD + d + 64];

    const float q0 = __half2float(qkv[p0]), q1 = __half2float(qkv[p1]);
    qkv[p0] = __float2half_rn(q0 * c0 - q1 * s0);
    qkv[p1] = __float2half_rn(q1 * c1 + q0 * s1);
    const float k0 = __half2float(qkv[p0 + D]), k1 = __half2float(qkv[p1 + D]);
    qkv[p0 + D] = __float2half_rn(k0 * c0 - k1 * s0);
    qkv[p1 + D] = __float2half_rn(k1 * c1 + k0 * s1);
}

// ---------------- launch ---------------------------------------------------
extern "C" void kernel_launch(void* const* d_in, const int* in_sizes, int n_in,
                              void* d_out, int out_size)
{
    const float* x    = (const float*)d_in[0];
    const float* fcos = (const float*)d_in[2];
    const float* fsin = (const float*)d_in[3];
    const float* wq   = (const float*)d_in[4];
    const float* wk   = (const float*)d_in[5];
    const float* wv   = (const float*)d_in[6];
    const float* wo   = (const float*)d_in[7];
    const float* w1   = (const float*)d_in[8];
    const float* w2   = (const float*)d_in[9];
    const float* w3   = (const float*)d_in[10];
    const float* anw  = (const float*)d_in[11];
    const float* fnw  = (const float*)d_in[12];
    float* out = (float*)d_out;

    float *x1;
    hlf *qkvh, *nxh, *ath, *nx2h, *gh;
    hlf *wqkvh, *woh, *w13h, *w2h;

    cudaGetSymbolAddress((void**)&x1,   g_x1);
    cudaGetSymbolAddress((void**)&qkvh, g_qkvh);
    cudaGetSymbolAddress((void**)&nxh,  g_nxh);
    cudaGetSymbolAddress((void**)&ath,  g_ath);
    cudaGetSymbolAddress((void**)&nx2h, g_nx2h);
    cudaGetSymbolAddress((void**)&gh,   g_gh);
    cudaGetSymbolAddress((void**)&wqkvh, g_wqkvh);
    cudaGetSymbolAddress((void**)&woh,  g_woh);
    cudaGetSymbolAddress((void**)&w13h, g_w13h);
    cudaGetSymbolAddress((void**)&w2h,  g_w2h);

    cudaFuncSetAttribute(tc8_gemm,
        cudaFuncAttributeMaxDynamicSharedMemorySize, GSMEM);
    cudaFuncSetAttribute(flash_attn,
        cudaFuncAttributeMaxDynamicSharedMemorySize, FSMEM);

    const dim3 gQkv(3 * D / 128, S / 128);       // 48x16
    const dim3 gProj(D / 128, S / 128);          // 16x16
    const dim3 gW13(2 * II / 128, S / 128);      // 128x16 (interleaved cols)
    const dim3 gFa (S / 128, H);                 // 16x16

    const int nDD = (D * D) / 4096;              // 4 float4/thread
    const int nDI = (D * II) / 4096;

    split_pack_h<<<nDD, 256>>>(wq, wqkvh, D, 3 * D, 0);
    split_pack_h<<<nDD, 256>>>(wk, wqkvh, D, 3 * D, D);
    split_pack_h<<<nDD, 256>>>(wv, wqkvh, D, 3 * D, 2 * D);
    split_pack_h<<<nDD, 256>>>(wo, woh, D, D, 0);
    pack_w13i<<<nDI, 256>>>(w1, w3, w13h);
    split_pack_h<<<nDI, 256>>>(w2, w2h, D, D, 0);

    rmsnorm_h<<<S, 256>>>(x, anw, nxh);

    // qkv projection -> fp16 [S, 3D]
    tc8_gemm<<<gQkv, 256, GSMEM>>>(nxh, D, wqkvh, 3 * D,
                                   nullptr, 0, nullptr, qkvh, 3 * D, D, 0);

    rope_inplace_h<<<(S * D / 2) / 256, 256>>>(qkvh, fcos, fsin);

    flash_attn<<<gFa, 256, FSMEM>>>(qkvh, ath);

    tc8_gemm<<<gProj, 256, GSMEM>>>(ath, D, woh, D,
                                    x, D, x1, nullptr, D, D, 0);

    rmsnorm_h<<<S, 256>>>(x1, fnw, nx2h);

    // fused w13 + silu -> fp16 gh [S, II]
    tc8_gemm<<<gW13, 256, GSMEM>>>(nx2h, D, w13h, 2 * II,
                                   nullptr, 0, nullptr, gh, II, D, 1);

    tc8_gemm<<<gProj, 256, GSMEM>>>(gh, II, w2h, D,
                                    x1, D, out, nullptr, D, II, 0);
}